// round 13
// baseline (speedup 1.0000x reference)
#include <cuda_runtime.h>
#include <cuda_bf16.h>
#include <math.h>
#include <stdint.h>

#define B_  4
#define S_  2048
#define D_  1024
#define H_  16
#define HD_ 64
#define NROWS (B_*S_)                       // 8192
#define NPLANE ((size_t)B_*H_*S_*HD_)       // 8388608
#define NXE   ((size_t)NROWS*D_)            // 8388608
#define NWE   ((size_t)D_*D_)               // 1048576

// Scratch (allocation-free __device__ globals)
__device__ __align__(16) __nv_bfloat16 g_X3h[3][NXE], g_X3l[3][NXE];
__device__ __align__(16) __nv_bfloat16 g_W4h[4][NWE], g_W4l[4][NWE];
__device__ __align__(16) __nv_bfloat16 g_P3h[3][NPLANE], g_P3l[3][NPLANE]; // q,k,v head-split
__device__ __align__(16) __nv_bfloat16 g_yh[NXE], g_yl[NXE];

// ---------------------------------------------------------------------------
// Helpers (baseline PTX only)
// ---------------------------------------------------------------------------
__device__ __forceinline__ uint32_t smem_u32(const void* p) {
    return (uint32_t)__cvta_generic_to_shared(p);
}
__device__ __forceinline__ void ldmx4(uint32_t* d, uint32_t addr) {
    asm volatile("ldmatrix.sync.aligned.m8n8.x4.shared.b16 {%0,%1,%2,%3}, [%4];"
                 : "=r"(d[0]), "=r"(d[1]), "=r"(d[2]), "=r"(d[3]) : "r"(addr));
}
__device__ __forceinline__ void ldmx4t(uint32_t* d, uint32_t addr) {
    asm volatile("ldmatrix.sync.aligned.m8n8.x4.trans.shared.b16 {%0,%1,%2,%3}, [%4];"
                 : "=r"(d[0]), "=r"(d[1]), "=r"(d[2]), "=r"(d[3]) : "r"(addr));
}
__device__ __forceinline__ void ldmx2(uint32_t* d, uint32_t addr) {
    asm volatile("ldmatrix.sync.aligned.m8n8.x2.shared.b16 {%0,%1}, [%2];"
                 : "=r"(d[0]), "=r"(d[1]) : "r"(addr));
}
__device__ __forceinline__ void mma16816(float* c, const uint32_t* a, const uint32_t* b) {
    asm volatile("mma.sync.aligned.m16n8k16.row.col.f32.bf16.bf16.f32 "
                 "{%0,%1,%2,%3}, {%4,%5,%6,%7}, {%8,%9}, {%0,%1,%2,%3};"
                 : "+f"(c[0]), "+f"(c[1]), "+f"(c[2]), "+f"(c[3])
                 : "r"(a[0]), "r"(a[1]), "r"(a[2]), "r"(a[3]), "r"(b[0]), "r"(b[1]));
}
__device__ __forceinline__ void cp16(uint32_t dst, const void* src) {
    asm volatile("cp.async.cg.shared.global [%0], [%1], 16;" :: "r"(dst), "l"(src));
}
__device__ __forceinline__ void cp16p(void* dst, const void* src) {
    asm volatile("cp.async.cg.shared.global [%0], [%1], 16;"
                 :: "r"(smem_u32(dst)), "l"(src));
}
__device__ __forceinline__ void cpcommit() { asm volatile("cp.async.commit_group;"); }
__device__ __forceinline__ void cpwait0()  { asm volatile("cp.async.wait_group 0;"); }
__device__ __forceinline__ void cpwait1()  { asm volatile("cp.async.wait_group 1;"); }

__device__ __forceinline__ void pack2(float a, float b, uint32_t& hi, uint32_t& lo) {
    __nv_bfloat162 h = __floats2bfloat162_rn(a, b);
    float ra = a - __bfloat162float(h.x);
    float rb = b - __bfloat162float(h.y);
    __nv_bfloat162 l2 = __floats2bfloat162_rn(ra, rb);
    hi = *(uint32_t*)&h; lo = *(uint32_t*)&l2;
}

#define SWZ128(x) ((x) ^ (((x) >> 3) & 0x70))

// ===========================================================================
// Batched splits: fp32 -> bf16 hi/lo planes
// ===========================================================================
__global__ __launch_bounds__(256)
void split_x3(const float* __restrict__ q, const float* __restrict__ k,
              const float* __restrict__ v, int n4)
{
    const int z = blockIdx.y;
    const float* x = (z == 0) ? q : (z == 1) ? k : v;
    int i = blockIdx.x * blockDim.x + threadIdx.x;
    if (i >= n4) return;
    float4 val = ((const float4*)x)[i];
    uint32_t h0, l0, h1, l1;
    pack2(val.x, val.y, h0, l0);
    pack2(val.z, val.w, h1, l1);
    ((uint2*)g_X3h[z])[i] = make_uint2(h0, h1);
    ((uint2*)g_X3l[z])[i] = make_uint2(l0, l1);
}

__global__ __launch_bounds__(256)
void split_w4(const float* __restrict__ Wq, const float* __restrict__ Wk,
              const float* __restrict__ Wv, const float* __restrict__ Wo, int n4)
{
    const int z = blockIdx.y;
    const float* x = (z == 0) ? Wq : (z == 1) ? Wk : (z == 2) ? Wv : Wo;
    int i = blockIdx.x * blockDim.x + threadIdx.x;
    if (i >= n4) return;
    float4 val = ((const float4*)x)[i];
    uint32_t h0, l0, h1, l1;
    pack2(val.x, val.y, h0, l0);
    pack2(val.z, val.w, h1, l1);
    ((uint2*)g_W4h[z])[i] = make_uint2(h0, h1);
    ((uint2*)g_W4l[z])[i] = make_uint2(l0, l1);
}

// ===========================================================================
// Projection GEMM core v3: 256x128 CTA tile, warp tile 64x64 (8 warps = 4x2),
// K-chunks of 64, 2-stage cp.async, SW128 swizzle. bf16x3 compensated.
// ===========================================================================
#define APLANE_ 32768                 // 256 rows * 128 B
#define BPLANE_ 16384                 // 128 rows * 128 B
#define PSTG_   (2*APLANE_ + 2*BPLANE_)   // 98304 B per stage
#define PNKC_   (D_/64)               // 16 chunks
#define PROJ_SMEM (2*PSTG_ + 1024)    // 197632 B

template<bool SPLIT>
__device__ __forceinline__ void proj_core(
    const __nv_bfloat16* __restrict__ Xh, const __nv_bfloat16* __restrict__ Xl,
    const __nv_bfloat16* __restrict__ Wh, const __nv_bfloat16* __restrict__ Wl,
    const float* __restrict__ bias, float* __restrict__ outF,
    __nv_bfloat16* __restrict__ hiP, __nv_bfloat16* __restrict__ loP,
    char* dsm_raw)
{
    const uint32_t dbase = (smem_u32(dsm_raw) + 1023) & ~1023u;

    const int t = threadIdx.x, lane = t & 31, warp = t >> 5;
    const int wm = warp & 3;          // 0..3 (64-row group)
    const int wn = warp >> 2;         // 0..1 (64-col group)
    const int rowBase = blockIdx.y * 256, colBase = blockIdx.x * 128;

    // A loader: thread t owns row t of 256, 8 x 16B units per plane
    const __nv_bfloat16* xp = Xh + (size_t)(rowBase + t) * D_;
    const __nv_bfloat16* xq = Xl + (size_t)(rowBase + t) * D_;
    const uint32_t arb = (uint32_t)t * 128;
    // B loader: row = t>>1 of 128, 4 x 16B units per plane
    const int bldr = t >> 1;
    const int bldc0 = (t & 1) * 4;
    const __nv_bfloat16* wp = Wh + (size_t)(colBase + bldr) * D_;
    const __nv_bfloat16* wq = Wl + (size_t)(colBase + bldr) * D_;
    const uint32_t brb = (uint32_t)bldr * 128;

    auto load_chunk = [&](int chunk, uint32_t stg) {
        const int k0 = chunk * 64;
        #pragma unroll
        for (int u = 0; u < 8; u++) {
            const uint32_t so = SWZ128(arb + u * 16);
            cp16(stg + 0*APLANE_ + so, xp + k0 + u*8);
            cp16(stg + 1*APLANE_ + so, xq + k0 + u*8);
        }
        #pragma unroll
        for (int u = 0; u < 4; u++) {
            const int c16 = bldc0 + u;
            const uint32_t so = SWZ128(brb + c16 * 16);
            cp16(stg + 2*APLANE_ + 0*BPLANE_ + so, wp + k0 + c16*8);
            cp16(stg + 2*APLANE_ + 1*BPLANE_ + so, wq + k0 + c16*8);
        }
        cpcommit();
    };

    load_chunk(0, dbase + 0*PSTG_);
    load_chunk(1, dbase + 1*PSTG_);

    float acc[4][8][4];
    #pragma unroll
    for (int i = 0; i < 4; i++)
        #pragma unroll
        for (int j = 0; j < 8; j++)
            #pragma unroll
            for (int f = 0; f < 4; f++) acc[i][j][f] = 0.f;

    const uint32_t arow = (uint32_t)(wm*64 + (lane & 15));
    const uint32_t acolu = (uint32_t)(lane >> 4);
    const uint32_t brow = (uint32_t)(wn*64 + (lane & 7));
    const uint32_t bcolu = (uint32_t)((lane >> 3) & 1);

    for (int it = 0; it < PNKC_; it++) {
        const uint32_t stg = dbase + (uint32_t)(it & 1) * PSTG_;

        if (it < PNKC_ - 1) cpwait1(); else cpwait0();
        __syncthreads();

        const uint32_t Ah = stg, Al = stg + APLANE_;
        const uint32_t Bh = stg + 2*APLANE_, Bl = stg + 2*APLANE_ + BPLANE_;

        #pragma unroll
        for (int ks = 0; ks < 4; ks++) {
            uint32_t ah[4][4], al[4][4];
            #pragma unroll
            for (int i = 0; i < 4; i++) {
                const uint32_t off = SWZ128((arow + i*16)*128 + ks*32 + acolu*16);
                ldmx4(ah[i], Ah + off);
                ldmx4(al[i], Al + off);
            }
            // process B in two j-halves to cap live registers
            #pragma unroll
            for (int jj = 0; jj < 2; jj++) {
                uint32_t bh[4][2], bl[4][2];
                #pragma unroll
                for (int j = 0; j < 4; j++) {
                    const uint32_t off = SWZ128((brow + (jj*4 + j)*8)*128 + ks*32 + bcolu*16);
                    ldmx2(bh[j], Bh + off);
                    ldmx2(bl[j], Bl + off);
                }
                #pragma unroll
                for (int i = 0; i < 4; i++)
                    #pragma unroll
                    for (int j = 0; j < 4; j++) {
                        mma16816(acc[i][jj*4 + j], ah[i], bh[j]);
                        mma16816(acc[i][jj*4 + j], ah[i], bl[j]);
                        mma16816(acc[i][jj*4 + j], al[i], bh[j]);
                    }
            }
        }
        __syncthreads();
        if (it + 2 < PNKC_) load_chunk(it + 2, stg);
    }

    const int g = lane >> 2, lmb = lane & 3;
    #pragma unroll
    for (int i = 0; i < 4; i++)
        #pragma unroll
        for (int j = 0; j < 8; j++) {
            const int col = colBase + wn*64 + j*8 + lmb*2;
            const float b0 = bias[col], b1 = bias[col+1];
            #pragma unroll
            for (int r = 0; r < 2; r++) {
                const int row = rowBase + wm*64 + i*16 + g + 8*r;
                float v0 = acc[i][j][2*r+0] + b0;  v0 = fmaxf(v0, 0.f);
                float v1 = acc[i][j][2*r+1] + b1;  v1 = fmaxf(v1, 0.f);
                if (SPLIT) {
                    uint32_t hi, lo; pack2(v0, v1, hi, lo);
                    const int hh = col >> 6, hd = col & 63;
                    const int bb = row >> 11, ss = row & (S_ - 1);
                    const size_t idx = ((size_t)((bb*H_ + hh)*S_) + ss)*HD_ + hd;
                    *(uint32_t*)(hiP + idx) = hi;
                    *(uint32_t*)(loP + idx) = lo;
                } else {
                    float2 o; o.x = v0; o.y = v1;
                    *(float2*)(outF + (size_t)row * D_ + col) = o;
                }
            }
        }
}

// Batched QKV projection: grid (8, 32, 3); z selects input/weight/output set.
__global__ __launch_bounds__(256)
void proj_qkv(const float* __restrict__ bq, const float* __restrict__ bk,
              const float* __restrict__ bv)
{
    extern __shared__ char dsm_raw[];
    const int z = blockIdx.z;
    const float* bias = (z == 0) ? bq : (z == 1) ? bk : bv;
    proj_core<true>(g_X3h[z], g_X3l[z], g_W4h[z], g_W4l[z],
                    bias, nullptr, g_P3h[z], g_P3l[z], dsm_raw);
}

// Output projection: consumes y planes, writes fp32 out.
__global__ __launch_bounds__(256)
void proj_out(const float* __restrict__ bo, float* __restrict__ out)
{
    extern __shared__ char dsm_raw[];
    proj_core<false>(g_yh, g_yl, g_W4h[3], g_W4l[3],
                     bo, out, nullptr, nullptr, dsm_raw);
}

// ===========================================================================
// Flash attention (R12-proven, unchanged): 128 threads, 64 q rows/CTA.
// KV tiles of 64 double-buffered; bf16x3 compensated QK^T & PV.
// ===========================================================================
#define KSTR 72
#define PL_  (64*KSTR)
#define STAGE_ (4*PL_)
#define NT_ (S_/64)
#define ATTN_SMEM (2*STAGE_*(int)sizeof(__nv_bfloat16))   // 73728 B

__global__ __launch_bounds__(128)
void attn_mma()
{
    extern __shared__ __nv_bfloat16 sm[];
    const int t = threadIdx.x, lane = t & 31, w = t >> 5;
    const int bh = blockIdx.y, qbase = blockIdx.x * 64;
    const int g = lane >> 2, lmb = lane & 3;

    __nv_bfloat16* st0 = sm;
    __nv_bfloat16* st1 = sm + STAGE_;
    const size_t base = (size_t)bh * S_;

    const __nv_bfloat16* qhi = g_P3h[0]; const __nv_bfloat16* qlo = g_P3l[0];
    const __nv_bfloat16* khi = g_P3h[1]; const __nv_bfloat16* klo = g_P3l[1];
    const __nv_bfloat16* vhi = g_P3h[2]; const __nv_bfloat16* vlo = g_P3l[2];

    // KV tile 0 -> st0
    #pragma unroll
    for (int i = 0; i < 4; i++) {
        const int id = t + 128*i, r = id >> 3, c = (id & 7) * 8;
        const size_t go = (base + r) * HD_ + c;
        cp16p(st0 + 0*PL_ + r*KSTR + c, khi + go);
        cp16p(st0 + 1*PL_ + r*KSTR + c, klo + go);
        cp16p(st0 + 2*PL_ + r*KSTR + c, vhi + go);
        cp16p(st0 + 3*PL_ + r*KSTR + c, vlo + go);
    }
    cpcommit();
    // Q tile -> st1 (planes 0,1)
    #pragma unroll
    for (int i = 0; i < 4; i++) {
        const int id = t + 128*i, r = id >> 3, c = (id & 7) * 8;
        const size_t go = (base + qbase + r) * HD_ + c;
        cp16p(st1 + 0*PL_ + r*KSTR + c, qhi + go);
        cp16p(st1 + 1*PL_ + r*KSTR + c, qlo + go);
    }
    cpcommit();
    cpwait0();
    __syncthreads();

    uint32_t qh[4][4], ql[4][4];
    {
        const int arow = 16*w + (lane & 15);
        const int acol = (lane >> 4) * 8;
        #pragma unroll
        for (int kc = 0; kc < 4; kc++) {
            ldmx4(qh[kc], smem_u32(st1 + 0*PL_ + arow*KSTR + kc*16 + acol));
            ldmx4(ql[kc], smem_u32(st1 + 1*PL_ + arow*KSTR + kc*16 + acol));
        }
    }
    __syncthreads();   // st1 free for KV tile 1

    float o[8][4];
    #pragma unroll
    for (int j = 0; j < 8; j++)
        #pragma unroll
        for (int f = 0; f < 4; f++) o[j][f] = 0.f;
    float m_run[2] = {-1e30f, -1e30f}, l_run[2] = {0.f, 0.f};

    const int krow = (lane & 7) + ((lane >> 4) & 1) * 8;
    const int kcsel = ((lane >> 3) & 1) * 8;
    const int vrow = lane & 15;
    const int vcsel = ((lane >> 4) & 1) * 8;

    for (int it = 0; it < NT_; it++) {
        const int cur = it & 1;
        __nv_bfloat16* stc = cur ? st1 : st0;
        if (it + 1 < NT_) {
            __nv_bfloat16* d = cur ? st0 : st1;
            #pragma unroll
            for (int i = 0; i < 4; i++) {
                const int id = t + 128*i, r = id >> 3, c = (id & 7) * 8;
                const size_t go = (base + (size_t)(it+1)*64 + r) * HD_ + c;
                cp16p(d + 0*PL_ + r*KSTR + c, khi + go);
                cp16p(d + 1*PL_ + r*KSTR + c, klo + go);
                cp16p(d + 2*PL_ + r*KSTR + c, vhi + go);
                cp16p(d + 3*PL_ + r*KSTR + c, vlo + go);
            }
            cpcommit();
            cpwait1();
        } else {
            cpwait0();
        }
        __syncthreads();

        __nv_bfloat16* Kh = stc;
        __nv_bfloat16* Kl = stc + PL_;
        __nv_bfloat16* Vh = stc + 2*PL_;
        __nv_bfloat16* Vl = stc + 3*PL_;

        // ---- S = Q K^T ----
        float s[8][4];
        #pragma unroll
        for (int j = 0; j < 8; j++)
            #pragma unroll
            for (int f = 0; f < 4; f++) s[j][f] = 0.f;

        #pragma unroll
        for (int kc = 0; kc < 4; kc++) {
            uint32_t kbh[4][4], kbl[4][4];
            #pragma unroll
            for (int j2 = 0; j2 < 4; j2++) {
                const uint32_t off = (16*j2 + krow)*KSTR + kc*16 + kcsel;
                ldmx4(kbh[j2], smem_u32(Kh + off));
                ldmx4(kbl[j2], smem_u32(Kl + off));
            }
            #pragma unroll
            for (int j2 = 0; j2 < 4; j2++) {
                mma16816(s[2*j2],   qh[kc], &kbh[j2][0]);
                mma16816(s[2*j2],   qh[kc], &kbl[j2][0]);
                mma16816(s[2*j2],   ql[kc], &kbh[j2][0]);
                mma16816(s[2*j2+1], qh[kc], &kbh[j2][2]);
                mma16816(s[2*j2+1], qh[kc], &kbl[j2][2]);
                mma16816(s[2*j2+1], ql[kc], &kbh[j2][2]);
            }
        }

        // ---- online softmax ----
        #pragma unroll
        for (int r = 0; r < 2; r++) {
            float mx = -1e30f;
            #pragma unroll
            for (int j = 0; j < 8; j++)
                mx = fmaxf(mx, fmaxf(s[j][2*r], s[j][2*r+1]));
            mx *= 0.125f;
            mx = fmaxf(mx, __shfl_xor_sync(0xffffffffu, mx, 1));
            mx = fmaxf(mx, __shfl_xor_sync(0xffffffffu, mx, 2));
            const float mnew = fmaxf(m_run[r], mx);
            const float corr = __expf(m_run[r] - mnew);
            m_run[r] = mnew;
            float rs = 0.f;
            #pragma unroll
            for (int j = 0; j < 8; j++) {
                float p0 = __expf(fmaf(s[j][2*r],   0.125f, -mnew));
                float p1 = __expf(fmaf(s[j][2*r+1], 0.125f, -mnew));
                s[j][2*r] = p0; s[j][2*r+1] = p1;
                rs += p0 + p1;
            }
            rs += __shfl_xor_sync(0xffffffffu, rs, 1);
            rs += __shfl_xor_sync(0xffffffffu, rs, 2);
            l_run[r] = l_run[r] * corr + rs;
            #pragma unroll
            for (int j = 0; j < 8; j++) { o[j][2*r] *= corr; o[j][2*r+1] *= corr; }
        }

        // ---- O += P V ----
        #pragma unroll
        for (int kc = 0; kc < 4; kc++) {
            uint32_t ph[4], pl[4];
            pack2(s[2*kc][0],   s[2*kc][1],   ph[0], pl[0]);
            pack2(s[2*kc][2],   s[2*kc][3],   ph[1], pl[1]);
            pack2(s[2*kc+1][0], s[2*kc+1][1], ph[2], pl[2]);
            pack2(s[2*kc+1][2], s[2*kc+1][3], ph[3], pl[3]);

            uint32_t vbh[4][4], vbl[4][4];
            #pragma unroll
            for (int j2 = 0; j2 < 4; j2++) {
                const uint32_t off = (16*kc + vrow)*KSTR + 16*j2 + vcsel;
                ldmx4t(vbh[j2], smem_u32(Vh + off));
                ldmx4t(vbl[j2], smem_u32(Vl + off));
            }
            #pragma unroll
            for (int j2 = 0; j2 < 4; j2++) {
                mma16816(o[2*j2],   ph, &vbh[j2][0]);
                mma16816(o[2*j2],   ph, &vbl[j2][0]);
                mma16816(o[2*j2],   pl, &vbh[j2][0]);
                mma16816(o[2*j2+1], ph, &vbh[j2][2]);
                mma16816(o[2*j2+1], ph, &vbl[j2][2]);
                mma16816(o[2*j2+1], pl, &vbh[j2][2]);
            }
        }
        __syncthreads();
    }

    // ---- epilogue: normalize + write y hi/lo planes [B,S,D] ----
    const int bb = bh >> 4, hh = bh & 15;
    #pragma unroll
    for (int r = 0; r < 2; r++) {
        const float inv = 1.f / l_run[r];
        const int row = qbase + 16*w + g + 8*r;
        const size_t iy = ((size_t)(bb * S_ + row)) * D_ + hh * HD_ + 2*lmb;
        #pragma unroll
        for (int j = 0; j < 8; j++) {
            uint32_t hi, lo;
            pack2(o[j][2*r] * inv, o[j][2*r+1] * inv, hi, lo);
            *(uint32_t*)(g_yh + iy + 8*j) = hi;
            *(uint32_t*)(g_yl + iy + 8*j) = lo;
        }
    }
}

// ===========================================================================
extern "C" void kernel_launch(void* const* d_in, const int* in_sizes, int n_in,
                              void* d_out, int out_size)
{
    const float* q  = (const float*)d_in[0];
    const float* k  = (const float*)d_in[1];
    const float* v  = (const float*)d_in[2];
    const float* Wq = (const float*)d_in[3];
    const float* bq = (const float*)d_in[4];
    const float* Wk = (const float*)d_in[5];
    const float* bk = (const float*)d_in[6];
    const float* Wv = (const float*)d_in[7];
    const float* bv = (const float*)d_in[8];
    const float* Wo = (const float*)d_in[9];
    const float* bo = (const float*)d_in[10];
    float* out = (float*)d_out;

    static bool attr_done = false;
    if (!attr_done) {
        cudaFuncSetAttribute(attn_mma, cudaFuncAttributeMaxDynamicSharedMemorySize, ATTN_SMEM);
        cudaFuncSetAttribute(proj_qkv, cudaFuncAttributeMaxDynamicSharedMemorySize, PROJ_SMEM);
        cudaFuncSetAttribute(proj_out, cudaFuncAttributeMaxDynamicSharedMemorySize, PROJ_SMEM);
        attr_done = true;
    }

    const int NX4 = (int)(NXE / 4);   // 2097152
    const int NW4 = (int)(NWE / 4);   // 262144

    // split all inputs
    split_x3<<<dim3((NX4 + 255)/256, 3), 256>>>(q, k, v, NX4);
    split_w4<<<dim3((NW4 + 255)/256, 4), 256>>>(Wq, Wk, Wv, Wo, NW4);

    // batched QKV projections (one launch, grid.z = 3), 256x128 tiles
    proj_qkv<<<dim3(D_/128, NROWS/256, 3), 256, PROJ_SMEM>>>(bq, bk, bv);

    // attention (64 q rows per CTA, 3 CTAs/SM)
    attn_mma<<<dim3(S_/64, B_*H_), 128, ATTN_SMEM>>>();

    // output projection
    proj_out<<<dim3(D_/128, NROWS/256), 256, PROJ_SMEM>>>(bo, out);
}

// round 14
// speedup vs baseline: 1.0704x; 1.0704x over previous
#include <cuda_runtime.h>
#include <cuda_bf16.h>
#include <math.h>
#include <stdint.h>

#define B_  4
#define S_  2048
#define D_  1024
#define H_  16
#define HD_ 64
#define NROWS (B_*S_)                       // 8192
#define NPLANE ((size_t)B_*H_*S_*HD_)       // 8388608
#define NXE   ((size_t)NROWS*D_)            // 8388608
#define NWE   ((size_t)D_*D_)               // 1048576

// Scratch (allocation-free __device__ globals)
__device__ __align__(16) __nv_bfloat16 g_X3h[3][NXE], g_X3l[3][NXE];
__device__ __align__(16) __nv_bfloat16 g_W4h[4][NWE], g_W4l[4][NWE];
__device__ __align__(16) __nv_bfloat16 g_P3h[3][NPLANE], g_P3l[3][NPLANE]; // q,k,v head-split
__device__ __align__(16) __nv_bfloat16 g_yh[NXE], g_yl[NXE];

// ---------------------------------------------------------------------------
// Helpers (baseline PTX only)
// ---------------------------------------------------------------------------
__device__ __forceinline__ uint32_t smem_u32(const void* p) {
    return (uint32_t)__cvta_generic_to_shared(p);
}
__device__ __forceinline__ void ldmx4(uint32_t* d, uint32_t addr) {
    asm volatile("ldmatrix.sync.aligned.m8n8.x4.shared.b16 {%0,%1,%2,%3}, [%4];"
                 : "=r"(d[0]), "=r"(d[1]), "=r"(d[2]), "=r"(d[3]) : "r"(addr));
}
__device__ __forceinline__ void ldmx4t(uint32_t* d, uint32_t addr) {
    asm volatile("ldmatrix.sync.aligned.m8n8.x4.trans.shared.b16 {%0,%1,%2,%3}, [%4];"
                 : "=r"(d[0]), "=r"(d[1]), "=r"(d[2]), "=r"(d[3]) : "r"(addr));
}
__device__ __forceinline__ void ldmx2(uint32_t* d, uint32_t addr) {
    asm volatile("ldmatrix.sync.aligned.m8n8.x2.shared.b16 {%0,%1}, [%2];"
                 : "=r"(d[0]), "=r"(d[1]) : "r"(addr));
}
__device__ __forceinline__ void mma16816(float* c, const uint32_t* a, const uint32_t* b) {
    asm volatile("mma.sync.aligned.m16n8k16.row.col.f32.bf16.bf16.f32 "
                 "{%0,%1,%2,%3}, {%4,%5,%6,%7}, {%8,%9}, {%0,%1,%2,%3};"
                 : "+f"(c[0]), "+f"(c[1]), "+f"(c[2]), "+f"(c[3])
                 : "r"(a[0]), "r"(a[1]), "r"(a[2]), "r"(a[3]), "r"(b[0]), "r"(b[1]));
}
__device__ __forceinline__ void cp16(uint32_t dst, const void* src) {
    asm volatile("cp.async.cg.shared.global [%0], [%1], 16;" :: "r"(dst), "l"(src));
}
__device__ __forceinline__ void cp16p(void* dst, const void* src) {
    asm volatile("cp.async.cg.shared.global [%0], [%1], 16;"
                 :: "r"(smem_u32(dst)), "l"(src));
}
__device__ __forceinline__ void cpcommit() { asm volatile("cp.async.commit_group;"); }
__device__ __forceinline__ void cpwait0()  { asm volatile("cp.async.wait_group 0;"); }
__device__ __forceinline__ void cpwait1()  { asm volatile("cp.async.wait_group 1;"); }
__device__ __forceinline__ void cpwait2()  { asm volatile("cp.async.wait_group 2;"); }

__device__ __forceinline__ void pack2(float a, float b, uint32_t& hi, uint32_t& lo) {
    __nv_bfloat162 h = __floats2bfloat162_rn(a, b);
    float ra = a - __bfloat162float(h.x);
    float rb = b - __bfloat162float(h.y);
    __nv_bfloat162 l2 = __floats2bfloat162_rn(ra, rb);
    hi = *(uint32_t*)&h; lo = *(uint32_t*)&l2;
}

#define SWZ128(x) ((x) ^ (((x) >> 3) & 0x70))
#define C2_ 0.180336879f   // 0.125 * log2(e)

// ===========================================================================
// Batched splits: fp32 -> bf16 hi/lo planes
// ===========================================================================
__global__ __launch_bounds__(256)
void split_x3(const float* __restrict__ q, const float* __restrict__ k,
              const float* __restrict__ v, int n4)
{
    const int z = blockIdx.y;
    const float* x = (z == 0) ? q : (z == 1) ? k : v;
    int i = blockIdx.x * blockDim.x + threadIdx.x;
    if (i >= n4) return;
    float4 val = ((const float4*)x)[i];
    uint32_t h0, l0, h1, l1;
    pack2(val.x, val.y, h0, l0);
    pack2(val.z, val.w, h1, l1);
    ((uint2*)g_X3h[z])[i] = make_uint2(h0, h1);
    ((uint2*)g_X3l[z])[i] = make_uint2(l0, l1);
}

__global__ __launch_bounds__(256)
void split_w4(const float* __restrict__ Wq, const float* __restrict__ Wk,
              const float* __restrict__ Wv, const float* __restrict__ Wo, int n4)
{
    const int z = blockIdx.y;
    const float* x = (z == 0) ? Wq : (z == 1) ? Wk : (z == 2) ? Wv : Wo;
    int i = blockIdx.x * blockDim.x + threadIdx.x;
    if (i >= n4) return;
    float4 val = ((const float4*)x)[i];
    uint32_t h0, l0, h1, l1;
    pack2(val.x, val.y, h0, l0);
    pack2(val.z, val.w, h1, l1);
    ((uint2*)g_W4h[z])[i] = make_uint2(h0, h1);
    ((uint2*)g_W4l[z])[i] = make_uint2(l0, l1);
}

// ===========================================================================
// Projection GEMM core (R12-proven): legacy mma.sync, bf16x3 compensated,
// pre-split inputs. CTA 128x128, 256 thr, K-chunks of 64, 3-stage cp.async,
// SW128 swizzle.
// ===========================================================================
#define PPLANE_ 16384                 // 128 rows * 128 B
#define PSTG_   (4*PPLANE_)           // 65536 B per stage
#define PNKC_   (D_/64)               // 16 chunks
#define PROJ_SMEM (3*PSTG_ + 1024)

template<bool SPLIT>
__device__ __forceinline__ void proj_core(
    const __nv_bfloat16* __restrict__ Xh, const __nv_bfloat16* __restrict__ Xl,
    const __nv_bfloat16* __restrict__ Wh, const __nv_bfloat16* __restrict__ Wl,
    const float* __restrict__ bias, float* __restrict__ outF,
    __nv_bfloat16* __restrict__ hiP, __nv_bfloat16* __restrict__ loP,
    char* dsm_raw)
{
    const uint32_t dbase = (smem_u32(dsm_raw) + 1023) & ~1023u;

    const int t = threadIdx.x, lane = t & 31, warp = t >> 5;
    const int wm = warp & 1, wn = warp >> 1;
    const int rowBase = blockIdx.y * 128, colBase = blockIdx.x * 128;

    const int ldr = t >> 1;
    const int ldc0 = (t & 1) * 4;
    const __nv_bfloat16* xp = Xh + (size_t)(rowBase + ldr) * D_;
    const __nv_bfloat16* xq = Xl + (size_t)(rowBase + ldr) * D_;
    const __nv_bfloat16* wp = Wh + (size_t)(colBase + ldr) * D_;
    const __nv_bfloat16* wq = Wl + (size_t)(colBase + ldr) * D_;
    const uint32_t rb = (uint32_t)ldr * 128;

    auto load_chunk = [&](int chunk, uint32_t stg) {
        const int k0 = chunk * 64;
        #pragma unroll
        for (int u = 0; u < 4; u++) {
            const int c16 = ldc0 + u;
            const uint32_t so = SWZ128(rb + c16 * 16);
            const int ge = k0 + c16 * 8;
            cp16(stg + 0*PPLANE_ + so, xp + ge);
            cp16(stg + 1*PPLANE_ + so, xq + ge);
            cp16(stg + 2*PPLANE_ + so, wp + ge);
            cp16(stg + 3*PPLANE_ + so, wq + ge);
        }
        cpcommit();
    };

    load_chunk(0, dbase + 0*PSTG_);
    load_chunk(1, dbase + 1*PSTG_);
    load_chunk(2, dbase + 2*PSTG_);

    float acc[4][4][4];
    #pragma unroll
    for (int i = 0; i < 4; i++)
        #pragma unroll
        for (int j = 0; j < 4; j++)
            #pragma unroll
            for (int f = 0; f < 4; f++) acc[i][j][f] = 0.f;

    const uint32_t arow = (uint32_t)(wm*64 + (lane & 15));
    const uint32_t acolu = (uint32_t)(lane >> 4);
    const uint32_t brow = (uint32_t)(wn*32 + (lane & 7));
    const uint32_t bcolu = (uint32_t)((lane >> 3) & 1);

    for (int it = 0; it < PNKC_; it++) {
        const uint32_t stg = dbase + (uint32_t)(it % 3) * PSTG_;

        if (it <= PNKC_ - 3)      cpwait2();
        else if (it == PNKC_ - 2) cpwait1();
        else                      cpwait0();
        __syncthreads();

        const uint32_t Ah = stg, Al = stg + PPLANE_;
        const uint32_t Bh = stg + 2*PPLANE_, Bl = stg + 3*PPLANE_;

        #pragma unroll
        for (int ks = 0; ks < 4; ks++) {
            uint32_t ah[4][4], al[4][4], bh[4][2], bl[4][2];
            #pragma unroll
            for (int i = 0; i < 4; i++) {
                const uint32_t off = SWZ128((arow + i*16)*128 + ks*32 + acolu*16);
                ldmx4(ah[i], Ah + off);
                ldmx4(al[i], Al + off);
            }
            #pragma unroll
            for (int j = 0; j < 4; j++) {
                const uint32_t off = SWZ128((brow + j*8)*128 + ks*32 + bcolu*16);
                ldmx2(bh[j], Bh + off);
                ldmx2(bl[j], Bl + off);
            }
            #pragma unroll
            for (int i = 0; i < 4; i++)
                #pragma unroll
                for (int j = 0; j < 4; j++) {
                    mma16816(acc[i][j], ah[i], bh[j]);
                    mma16816(acc[i][j], ah[i], bl[j]);
                    mma16816(acc[i][j], al[i], bh[j]);
                }
        }
        __syncthreads();
        if (it + 3 < PNKC_) load_chunk(it + 3, stg);
    }

    const int g = lane >> 2, lmb = lane & 3;
    #pragma unroll
    for (int i = 0; i < 4; i++)
        #pragma unroll
        for (int j = 0; j < 4; j++) {
            const int col = colBase + wn*32 + j*8 + lmb*2;
            const float b0 = bias[col], b1 = bias[col+1];
            #pragma unroll
            for (int r = 0; r < 2; r++) {
                const int row = rowBase + wm*64 + i*16 + g + 8*r;
                float v0 = acc[i][j][2*r+0] + b0;  v0 = fmaxf(v0, 0.f);
                float v1 = acc[i][j][2*r+1] + b1;  v1 = fmaxf(v1, 0.f);
                if (SPLIT) {
                    uint32_t hi, lo; pack2(v0, v1, hi, lo);
                    const int hh = col >> 6, hd = col & 63;
                    const int bb = row >> 11, ss = row & (S_ - 1);
                    const size_t idx = ((size_t)((bb*H_ + hh)*S_) + ss)*HD_ + hd;
                    *(uint32_t*)(hiP + idx) = hi;
                    *(uint32_t*)(loP + idx) = lo;
                } else {
                    float2 o; o.x = v0; o.y = v1;
                    *(float2*)(outF + (size_t)row * D_ + col) = o;
                }
            }
        }
}

// Batched QKV projection: grid (8, 64, 3); z selects input/weight/output set.
__global__ __launch_bounds__(256)
void proj_qkv(const float* __restrict__ bq, const float* __restrict__ bk,
              const float* __restrict__ bv)
{
    extern __shared__ char dsm_raw[];
    const int z = blockIdx.z;
    const float* bias = (z == 0) ? bq : (z == 1) ? bk : bv;
    proj_core<true>(g_X3h[z], g_X3l[z], g_W4h[z], g_W4l[z],
                    bias, nullptr, g_P3h[z], g_P3l[z], dsm_raw);
}

// Output projection: consumes y planes, writes fp32 out.
__global__ __launch_bounds__(256)
void proj_out(const float* __restrict__ bo, float* __restrict__ out)
{
    extern __shared__ char dsm_raw[];
    proj_core<false>(g_yh, g_yl, g_W4h[3], g_W4l[3],
                     bo, out, nullptr, nullptr, dsm_raw);
}

// ===========================================================================
// Flash attention: 128 threads, 64 q rows/CTA, 3 CTAs/SM.
// KV tiles of 64 double-buffered; bf16x3 compensated QK^T & PV.
// Softmax in exp2 domain + warp-uniform rescale skip.
// ===========================================================================
#define KSTR 72
#define PL_  (64*KSTR)
#define STAGE_ (4*PL_)
#define NT_ (S_/64)
#define ATTN_SMEM (2*STAGE_*(int)sizeof(__nv_bfloat16))   // 73728 B

__global__ __launch_bounds__(128)
void attn_mma()
{
    extern __shared__ __nv_bfloat16 sm[];
    const int t = threadIdx.x, lane = t & 31, w = t >> 5;
    const int bh = blockIdx.y, qbase = blockIdx.x * 64;
    const int g = lane >> 2, lmb = lane & 3;

    __nv_bfloat16* st0 = sm;
    __nv_bfloat16* st1 = sm + STAGE_;
    const size_t base = (size_t)bh * S_;

    const __nv_bfloat16* qhi = g_P3h[0]; const __nv_bfloat16* qlo = g_P3l[0];
    const __nv_bfloat16* khi = g_P3h[1]; const __nv_bfloat16* klo = g_P3l[1];
    const __nv_bfloat16* vhi = g_P3h[2]; const __nv_bfloat16* vlo = g_P3l[2];

    // KV tile 0 -> st0
    #pragma unroll
    for (int i = 0; i < 4; i++) {
        const int id = t + 128*i, r = id >> 3, c = (id & 7) * 8;
        const size_t go = (base + r) * HD_ + c;
        cp16p(st0 + 0*PL_ + r*KSTR + c, khi + go);
        cp16p(st0 + 1*PL_ + r*KSTR + c, klo + go);
        cp16p(st0 + 2*PL_ + r*KSTR + c, vhi + go);
        cp16p(st0 + 3*PL_ + r*KSTR + c, vlo + go);
    }
    cpcommit();
    // Q tile -> st1 (planes 0,1)
    #pragma unroll
    for (int i = 0; i < 4; i++) {
        const int id = t + 128*i, r = id >> 3, c = (id & 7) * 8;
        const size_t go = (base + qbase + r) * HD_ + c;
        cp16p(st1 + 0*PL_ + r*KSTR + c, qhi + go);
        cp16p(st1 + 1*PL_ + r*KSTR + c, qlo + go);
    }
    cpcommit();
    cpwait0();
    __syncthreads();

    uint32_t qh[4][4], ql[4][4];
    {
        const int arow = 16*w + (lane & 15);
        const int acol = (lane >> 4) * 8;
        #pragma unroll
        for (int kc = 0; kc < 4; kc++) {
            ldmx4(qh[kc], smem_u32(st1 + 0*PL_ + arow*KSTR + kc*16 + acol));
            ldmx4(ql[kc], smem_u32(st1 + 1*PL_ + arow*KSTR + kc*16 + acol));
        }
    }
    __syncthreads();   // st1 free for KV tile 1

    float o[8][4];
    #pragma unroll
    for (int j = 0; j < 8; j++)
        #pragma unroll
        for (int f = 0; f < 4; f++) o[j][f] = 0.f;
    float m_run[2] = {-1e30f, -1e30f}, l_run[2] = {0.f, 0.f};

    const int krow = (lane & 7) + ((lane >> 4) & 1) * 8;
    const int kcsel = ((lane >> 3) & 1) * 8;
    const int vrow = lane & 15;
    const int vcsel = ((lane >> 4) & 1) * 8;

    for (int it = 0; it < NT_; it++) {
        const int cur = it & 1;
        __nv_bfloat16* stc = cur ? st1 : st0;
        if (it + 1 < NT_) {
            __nv_bfloat16* d = cur ? st0 : st1;
            #pragma unroll
            for (int i = 0; i < 4; i++) {
                const int id = t + 128*i, r = id >> 3, c = (id & 7) * 8;
                const size_t go = (base + (size_t)(it+1)*64 + r) * HD_ + c;
                cp16p(d + 0*PL_ + r*KSTR + c, khi + go);
                cp16p(d + 1*PL_ + r*KSTR + c, klo + go);
                cp16p(d + 2*PL_ + r*KSTR + c, vhi + go);
                cp16p(d + 3*PL_ + r*KSTR + c, vlo + go);
            }
            cpcommit();
            cpwait1();
        } else {
            cpwait0();
        }
        __syncthreads();

        __nv_bfloat16* Kh = stc;
        __nv_bfloat16* Kl = stc + PL_;
        __nv_bfloat16* Vh = stc + 2*PL_;
        __nv_bfloat16* Vl = stc + 3*PL_;

        // ---- S = Q K^T ----
        float s[8][4];
        #pragma unroll
        for (int j = 0; j < 8; j++)
            #pragma unroll
            for (int f = 0; f < 4; f++) s[j][f] = 0.f;

        #pragma unroll
        for (int kc = 0; kc < 4; kc++) {
            uint32_t kbh[4][4], kbl[4][4];
            #pragma unroll
            for (int j2 = 0; j2 < 4; j2++) {
                const uint32_t off = (16*j2 + krow)*KSTR + kc*16 + kcsel;
                ldmx4(kbh[j2], smem_u32(Kh + off));
                ldmx4(kbl[j2], smem_u32(Kl + off));
            }
            #pragma unroll
            for (int j2 = 0; j2 < 4; j2++) {
                mma16816(s[2*j2],   qh[kc], &kbh[j2][0]);
                mma16816(s[2*j2],   qh[kc], &kbl[j2][0]);
                mma16816(s[2*j2],   ql[kc], &kbh[j2][0]);
                mma16816(s[2*j2+1], qh[kc], &kbh[j2][2]);
                mma16816(s[2*j2+1], qh[kc], &kbl[j2][2]);
                mma16816(s[2*j2+1], ql[kc], &kbh[j2][2]);
            }
        }

        // ---- online softmax (exp2 domain) ----
        #pragma unroll
        for (int r = 0; r < 2; r++) {
            float mx = -1e30f;
            #pragma unroll
            for (int j = 0; j < 8; j++)
                mx = fmaxf(mx, fmaxf(s[j][2*r], s[j][2*r+1]));
            mx *= C2_;
            mx = fmaxf(mx, __shfl_xor_sync(0xffffffffu, mx, 1));
            mx = fmaxf(mx, __shfl_xor_sync(0xffffffffu, mx, 2));
            const float mold = m_run[r];
            const float mnew = fmaxf(mold, mx);
            m_run[r] = mnew;
            float rs = 0.f;
            #pragma unroll
            for (int j = 0; j < 8; j++) {
                float p0 = exp2f(fmaf(s[j][2*r],   C2_, -mnew));
                float p1 = exp2f(fmaf(s[j][2*r+1], C2_, -mnew));
                s[j][2*r] = p0; s[j][2*r+1] = p1;
                rs += p0 + p1;
            }
            rs += __shfl_xor_sync(0xffffffffu, rs, 1);
            rs += __shfl_xor_sync(0xffffffffu, rs, 2);
            const float corr = exp2f(mold - mnew);   // ==1.0 exactly when no update
            l_run[r] = l_run[r] * corr + rs;
            if (__any_sync(0xffffffffu, mnew > mold)) {
                #pragma unroll
                for (int j = 0; j < 8; j++) { o[j][2*r] *= corr; o[j][2*r+1] *= corr; }
            }
        }

        // ---- O += P V ----
        #pragma unroll
        for (int kc = 0; kc < 4; kc++) {
            uint32_t ph[4], pl[4];
            pack2(s[2*kc][0],   s[2*kc][1],   ph[0], pl[0]);
            pack2(s[2*kc][2],   s[2*kc][3],   ph[1], pl[1]);
            pack2(s[2*kc+1][0], s[2*kc+1][1], ph[2], pl[2]);
            pack2(s[2*kc+1][2], s[2*kc+1][3], ph[3], pl[3]);

            uint32_t vbh[4][4], vbl[4][4];
            #pragma unroll
            for (int j2 = 0; j2 < 4; j2++) {
                const uint32_t off = (16*kc + vrow)*KSTR + 16*j2 + vcsel;
                ldmx4t(vbh[j2], smem_u32(Vh + off));
                ldmx4t(vbl[j2], smem_u32(Vl + off));
            }
            #pragma unroll
            for (int j2 = 0; j2 < 4; j2++) {
                mma16816(o[2*j2],   ph, &vbh[j2][0]);
                mma16816(o[2*j2],   ph, &vbl[j2][0]);
                mma16816(o[2*j2],   pl, &vbh[j2][0]);
                mma16816(o[2*j2+1], ph, &vbh[j2][2]);
                mma16816(o[2*j2+1], ph, &vbl[j2][2]);
                mma16816(o[2*j2+1], pl, &vbh[j2][2]);
            }
        }
        __syncthreads();
    }

    // ---- epilogue: normalize + write y hi/lo planes [B,S,D] ----
    const int bb = bh >> 4, hh = bh & 15;
    #pragma unroll
    for (int r = 0; r < 2; r++) {
        const float inv = 1.f / l_run[r];
        const int row = qbase + 16*w + g + 8*r;
        const size_t iy = ((size_t)(bb * S_ + row)) * D_ + hh * HD_ + 2*lmb;
        #pragma unroll
        for (int j = 0; j < 8; j++) {
            uint32_t hi, lo;
            pack2(o[j][2*r] * inv, o[j][2*r+1] * inv, hi, lo);
            *(uint32_t*)(g_yh + iy + 8*j) = hi;
            *(uint32_t*)(g_yl + iy + 8*j) = lo;
        }
    }
}

// ===========================================================================
extern "C" void kernel_launch(void* const* d_in, const int* in_sizes, int n_in,
                              void* d_out, int out_size)
{
    const float* q  = (const float*)d_in[0];
    const float* k  = (const float*)d_in[1];
    const float* v  = (const float*)d_in[2];
    const float* Wq = (const float*)d_in[3];
    const float* bq = (const float*)d_in[4];
    const float* Wk = (const float*)d_in[5];
    const float* bk = (const float*)d_in[6];
    const float* Wv = (const float*)d_in[7];
    const float* bv = (const float*)d_in[8];
    const float* Wo = (const float*)d_in[9];
    const float* bo = (const float*)d_in[10];
    float* out = (float*)d_out;

    static bool attr_done = false;
    if (!attr_done) {
        cudaFuncSetAttribute(attn_mma, cudaFuncAttributeMaxDynamicSharedMemorySize, ATTN_SMEM);
        cudaFuncSetAttribute(proj_qkv, cudaFuncAttributeMaxDynamicSharedMemorySize, PROJ_SMEM);
        cudaFuncSetAttribute(proj_out, cudaFuncAttributeMaxDynamicSharedMemorySize, PROJ_SMEM);
        attr_done = true;
    }

    const int NX4 = (int)(NXE / 4);   // 2097152
    const int NW4 = (int)(NWE / 4);   // 262144

    // split all inputs
    split_x3<<<dim3((NX4 + 255)/256, 3), 256>>>(q, k, v, NX4);
    split_w4<<<dim3((NW4 + 255)/256, 4), 256>>>(Wq, Wk, Wv, Wo, NW4);

    // batched QKV projections (one launch, grid.z = 3)
    proj_qkv<<<dim3(D_/128, NROWS/128, 3), 256, PROJ_SMEM>>>(bq, bk, bv);

    // attention (64 q rows per CTA, 3 CTAs/SM)
    attn_mma<<<dim3(S_/64, B_*H_), 128, ATTN_SMEM>>>();

    // output projection
    proj_out<<<dim3(D_/128, NROWS/128), 256, PROJ_SMEM>>>(bo, out);
}

// round 16
// speedup vs baseline: 1.0949x; 1.0229x over previous
#include <cuda_runtime.h>
#include <cuda_bf16.h>
#include <math.h>
#include <stdint.h>

#define B_  4
#define S_  2048
#define D_  1024
#define H_  16
#define HD_ 64
#define NROWS (B_*S_)                       // 8192
#define NPLANE ((size_t)B_*H_*S_*HD_)       // 8388608
#define NXE   ((size_t)NROWS*D_)            // 8388608
#define NWE   ((size_t)D_*D_)               // 1048576

// Scratch (allocation-free __device__ globals)
__device__ __align__(16) __nv_bfloat16 g_X3h[3][NXE], g_X3l[3][NXE];
__device__ __align__(16) __nv_bfloat16 g_W4h[4][NWE], g_W4l[4][NWE];
__device__ __align__(16) __nv_bfloat16 g_P3h[3][NPLANE], g_P3l[3][NPLANE]; // q,k,v head-split
__device__ __align__(16) __nv_bfloat16 g_yh[NXE], g_yl[NXE];

// ---------------------------------------------------------------------------
// Helpers (baseline PTX only)
// ---------------------------------------------------------------------------
__device__ __forceinline__ uint32_t smem_u32(const void* p) {
    return (uint32_t)__cvta_generic_to_shared(p);
}
__device__ __forceinline__ void ldmx4(uint32_t* d, uint32_t addr) {
    asm volatile("ldmatrix.sync.aligned.m8n8.x4.shared.b16 {%0,%1,%2,%3}, [%4];"
                 : "=r"(d[0]), "=r"(d[1]), "=r"(d[2]), "=r"(d[3]) : "r"(addr));
}
__device__ __forceinline__ void ldmx4t(uint32_t* d, uint32_t addr) {
    asm volatile("ldmatrix.sync.aligned.m8n8.x4.trans.shared.b16 {%0,%1,%2,%3}, [%4];"
                 : "=r"(d[0]), "=r"(d[1]), "=r"(d[2]), "=r"(d[3]) : "r"(addr));
}
__device__ __forceinline__ void ldmx2(uint32_t* d, uint32_t addr) {
    asm volatile("ldmatrix.sync.aligned.m8n8.x2.shared.b16 {%0,%1}, [%2];"
                 : "=r"(d[0]), "=r"(d[1]) : "r"(addr));
}
__device__ __forceinline__ void mma16816(float* c, const uint32_t* a, const uint32_t* b) {
    asm volatile("mma.sync.aligned.m16n8k16.row.col.f32.bf16.bf16.f32 "
                 "{%0,%1,%2,%3}, {%4,%5,%6,%7}, {%8,%9}, {%0,%1,%2,%3};"
                 : "+f"(c[0]), "+f"(c[1]), "+f"(c[2]), "+f"(c[3])
                 : "r"(a[0]), "r"(a[1]), "r"(a[2]), "r"(a[3]), "r"(b[0]), "r"(b[1]));
}
__device__ __forceinline__ void cp16(uint32_t dst, const void* src) {
    asm volatile("cp.async.cg.shared.global [%0], [%1], 16;" :: "r"(dst), "l"(src));
}
__device__ __forceinline__ void cp16p(void* dst, const void* src) {
    asm volatile("cp.async.cg.shared.global [%0], [%1], 16;"
                 :: "r"(smem_u32(dst)), "l"(src));
}
__device__ __forceinline__ void cpcommit() { asm volatile("cp.async.commit_group;"); }
__device__ __forceinline__ void cpwait0()  { asm volatile("cp.async.wait_group 0;"); }
__device__ __forceinline__ void cpwait1()  { asm volatile("cp.async.wait_group 1;"); }

__device__ __forceinline__ void pack2(float a, float b, uint32_t& hi, uint32_t& lo) {
    __nv_bfloat162 h = __floats2bfloat162_rn(a, b);
    float ra = a - __bfloat162float(h.x);
    float rb = b - __bfloat162float(h.y);
    __nv_bfloat162 l2 = __floats2bfloat162_rn(ra, rb);
    hi = *(uint32_t*)&h; lo = *(uint32_t*)&l2;
}

#define SWZ128(x) ((x) ^ (((x) >> 3) & 0x70))
#define C2_ 0.180336879f   // 0.125 * log2(e)

// ===========================================================================
// Batched splits: fp32 -> bf16 hi/lo planes
// ===========================================================================
__global__ __launch_bounds__(256)
void split_x3(const float* __restrict__ q, const float* __restrict__ k,
              const float* __restrict__ v, int n4)
{
    const int z = blockIdx.y;
    const float* x = (z == 0) ? q : (z == 1) ? k : v;
    int i = blockIdx.x * blockDim.x + threadIdx.x;
    if (i >= n4) return;
    float4 val = ((const float4*)x)[i];
    uint32_t h0, l0, h1, l1;
    pack2(val.x, val.y, h0, l0);
    pack2(val.z, val.w, h1, l1);
    ((uint2*)g_X3h[z])[i] = make_uint2(h0, h1);
    ((uint2*)g_X3l[z])[i] = make_uint2(l0, l1);
}

__global__ __launch_bounds__(256)
void split_w4(const float* __restrict__ Wq, const float* __restrict__ Wk,
              const float* __restrict__ Wv, const float* __restrict__ Wo, int n4)
{
    const int z = blockIdx.y;
    const float* x = (z == 0) ? Wq : (z == 1) ? Wk : (z == 2) ? Wv : Wo;
    int i = blockIdx.x * blockDim.x + threadIdx.x;
    if (i >= n4) return;
    float4 val = ((const float4*)x)[i];
    uint32_t h0, l0, h1, l1;
    pack2(val.x, val.y, h0, l0);
    pack2(val.z, val.w, h1, l1);
    ((uint2*)g_W4h[z])[i] = make_uint2(h0, h1);
    ((uint2*)g_W4l[z])[i] = make_uint2(l0, l1);
}

// ===========================================================================
// Projection GEMM core: legacy mma.sync, bf16x3 compensated, pre-split inputs.
// CTA 128x128, 256 thr, K-chunks of 64, 3-stage cp.async, SW128 swizzle.
// Single __syncthreads per iteration (prefetch into stage consumed last iter).
// ===========================================================================
#define PPLANE_ 16384                 // 128 rows * 128 B
#define PSTG_   (4*PPLANE_)           // 65536 B per stage
#define PNKC_   (D_/64)               // 16 chunks
#define PROJ_SMEM (3*PSTG_ + 1024)

template<bool SPLIT>
__device__ __forceinline__ void proj_core(
    const __nv_bfloat16* __restrict__ Xh, const __nv_bfloat16* __restrict__ Xl,
    const __nv_bfloat16* __restrict__ Wh, const __nv_bfloat16* __restrict__ Wl,
    const float* __restrict__ bias, float* __restrict__ outF,
    __nv_bfloat16* __restrict__ hiP, __nv_bfloat16* __restrict__ loP,
    char* dsm_raw)
{
    const uint32_t dbase = (smem_u32(dsm_raw) + 1023) & ~1023u;

    const int t = threadIdx.x, lane = t & 31, warp = t >> 5;
    const int wm = warp & 1, wn = warp >> 1;
    const int rowBase = blockIdx.y * 128, colBase = blockIdx.x * 128;

    const int ldr = t >> 1;
    const int ldc0 = (t & 1) * 4;
    const __nv_bfloat16* xp = Xh + (size_t)(rowBase + ldr) * D_;
    const __nv_bfloat16* xq = Xl + (size_t)(rowBase + ldr) * D_;
    const __nv_bfloat16* wp = Wh + (size_t)(colBase + ldr) * D_;
    const __nv_bfloat16* wq = Wl + (size_t)(colBase + ldr) * D_;
    const uint32_t rb = (uint32_t)ldr * 128;

    auto load_chunk = [&](int chunk, uint32_t stg) {
        const int k0 = chunk * 64;
        #pragma unroll
        for (int u = 0; u < 4; u++) {
            const int c16 = ldc0 + u;
            const uint32_t so = SWZ128(rb + c16 * 16);
            const int ge = k0 + c16 * 8;
            cp16(stg + 0*PPLANE_ + so, xp + ge);
            cp16(stg + 1*PPLANE_ + so, xq + ge);
            cp16(stg + 2*PPLANE_ + so, wp + ge);
            cp16(stg + 3*PPLANE_ + so, wq + ge);
        }
        cpcommit();
    };

    load_chunk(0, dbase + 0*PSTG_);
    load_chunk(1, dbase + 1*PSTG_);

    float acc[4][4][4];
    #pragma unroll
    for (int i = 0; i < 4; i++)
        #pragma unroll
        for (int j = 0; j < 4; j++)
            #pragma unroll
            for (int f = 0; f < 4; f++) acc[i][j][f] = 0.f;

    const uint32_t arow = (uint32_t)(wm*64 + (lane & 15));
    const uint32_t acolu = (uint32_t)(lane >> 4);
    const uint32_t brow = (uint32_t)(wn*32 + (lane & 7));
    const uint32_t bcolu = (uint32_t)((lane >> 3) & 1);

    for (int it = 0; it < PNKC_; it++) {
        const uint32_t stg = dbase + (uint32_t)(it % 3) * PSTG_;

        if (it < PNKC_ - 1) cpwait1(); else cpwait0();
        __syncthreads();
        // prefetch chunk it+2 into stage (it+2)%3 == (it-1)%3 (consumed last iter;
        // the sync above proved every warp finished it)
        if (it + 2 < PNKC_)
            load_chunk(it + 2, dbase + (uint32_t)((it + 2) % 3) * PSTG_);

        const uint32_t Ah = stg, Al = stg + PPLANE_;
        const uint32_t Bh = stg + 2*PPLANE_, Bl = stg + 3*PPLANE_;

        #pragma unroll
        for (int ks = 0; ks < 4; ks++) {
            uint32_t ah[4][4], al[4][4], bh[4][2], bl[4][2];
            #pragma unroll
            for (int i = 0; i < 4; i++) {
                const uint32_t off = SWZ128((arow + i*16)*128 + ks*32 + acolu*16);
                ldmx4(ah[i], Ah + off);
                ldmx4(al[i], Al + off);
            }
            #pragma unroll
            for (int j = 0; j < 4; j++) {
                const uint32_t off = SWZ128((brow + j*8)*128 + ks*32 + bcolu*16);
                ldmx2(bh[j], Bh + off);
                ldmx2(bl[j], Bl + off);
            }
            #pragma unroll
            for (int i = 0; i < 4; i++)
                #pragma unroll
                for (int j = 0; j < 4; j++) {
                    mma16816(acc[i][j], ah[i], bh[j]);
                    mma16816(acc[i][j], ah[i], bl[j]);
                    mma16816(acc[i][j], al[i], bh[j]);
                }
        }
        // no trailing sync
    }

    const int g = lane >> 2, lmb = lane & 3;
    #pragma unroll
    for (int i = 0; i < 4; i++)
        #pragma unroll
        for (int j = 0; j < 4; j++) {
            const int col = colBase + wn*32 + j*8 + lmb*2;
            const float b0 = bias[col], b1 = bias[col+1];
            #pragma unroll
            for (int r = 0; r < 2; r++) {
                const int row = rowBase + wm*64 + i*16 + g + 8*r;
                float v0 = acc[i][j][2*r+0] + b0;  v0 = fmaxf(v0, 0.f);
                float v1 = acc[i][j][2*r+1] + b1;  v1 = fmaxf(v1, 0.f);
                if (SPLIT) {
                    uint32_t hi, lo; pack2(v0, v1, hi, lo);
                    const int hh = col >> 6, hd = col & 63;
                    const int bb = row >> 11, ss = row & (S_ - 1);
                    const size_t idx = ((size_t)((bb*H_ + hh)*S_) + ss)*HD_ + hd;
                    *(uint32_t*)(hiP + idx) = hi;
                    *(uint32_t*)(loP + idx) = lo;
                } else {
                    float2 o; o.x = v0; o.y = v1;
                    *(float2*)(outF + (size_t)row * D_ + col) = o;
                }
            }
        }
}

// Batched QKV projection: grid (8, 64, 3); z selects input/weight/output set.
__global__ __launch_bounds__(256)
void proj_qkv(const float* __restrict__ bq, const float* __restrict__ bk,
              const float* __restrict__ bv)
{
    extern __shared__ char dsm_raw[];
    const int z = blockIdx.z;
    const float* bias = (z == 0) ? bq : (z == 1) ? bk : bv;
    proj_core<true>(g_X3h[z], g_X3l[z], g_W4h[z], g_W4l[z],
                    bias, nullptr, g_P3h[z], g_P3l[z], dsm_raw);
}

// Output projection: consumes y planes, writes fp32 out.
__global__ __launch_bounds__(256)
void proj_out(const float* __restrict__ bo, float* __restrict__ out)
{
    extern __shared__ char dsm_raw[];
    proj_core<false>(g_yh, g_yl, g_W4h[3], g_W4l[3],
                     bo, out, nullptr, nullptr, dsm_raw);
}

// ===========================================================================
// Flash attention: 128 threads, 64 q rows/CTA, 3 CTAs/SM.
// KV tiles of 64 double-buffered; bf16x3 compensated QK^T & PV.
// Softmax in exp2 domain + warp-uniform rescale skip.
// Single __syncthreads per iteration.
// ===========================================================================
#define KSTR 72
#define PL_  (64*KSTR)
#define STAGE_ (4*PL_)
#define NT_ (S_/64)
#define ATTN_SMEM (2*STAGE_*(int)sizeof(__nv_bfloat16))   // 73728 B

__global__ __launch_bounds__(128)
void attn_mma()
{
    extern __shared__ __nv_bfloat16 sm[];
    const int t = threadIdx.x, lane = t & 31, w = t >> 5;
    const int bh = blockIdx.y, qbase = blockIdx.x * 64;
    const int g = lane >> 2, lmb = lane & 3;

    __nv_bfloat16* st0 = sm;
    __nv_bfloat16* st1 = sm + STAGE_;
    const size_t base = (size_t)bh * S_;

    const __nv_bfloat16* qhi = g_P3h[0]; const __nv_bfloat16* qlo = g_P3l[0];
    const __nv_bfloat16* khi = g_P3h[1]; const __nv_bfloat16* klo = g_P3l[1];
    const __nv_bfloat16* vhi = g_P3h[2]; const __nv_bfloat16* vlo = g_P3l[2];

    // KV tile 0 -> st0
    #pragma unroll
    for (int i = 0; i < 4; i++) {
        const int id = t + 128*i, r = id >> 3, c = (id & 7) * 8;
        const size_t go = (base + r) * HD_ + c;
        cp16p(st0 + 0*PL_ + r*KSTR + c, khi + go);
        cp16p(st0 + 1*PL_ + r*KSTR + c, klo + go);
        cp16p(st0 + 2*PL_ + r*KSTR + c, vhi + go);
        cp16p(st0 + 3*PL_ + r*KSTR + c, vlo + go);
    }
    cpcommit();
    // Q tile -> st1 (planes 0,1)
    #pragma unroll
    for (int i = 0; i < 4; i++) {
        const int id = t + 128*i, r = id >> 3, c = (id & 7) * 8;
        const size_t go = (base + qbase + r) * HD_ + c;
        cp16p(st1 + 0*PL_ + r*KSTR + c, qhi + go);
        cp16p(st1 + 1*PL_ + r*KSTR + c, qlo + go);
    }
    cpcommit();
    cpwait0();
    __syncthreads();

    uint32_t qh[4][4], ql[4][4];
    {
        const int arow = 16*w + (lane & 15);
        const int acol = (lane >> 4) * 8;
        #pragma unroll
        for (int kc = 0; kc < 4; kc++) {
            ldmx4(qh[kc], smem_u32(st1 + 0*PL_ + arow*KSTR + kc*16 + acol));
            ldmx4(ql[kc], smem_u32(st1 + 1*PL_ + arow*KSTR + kc*16 + acol));
        }
    }
    __syncthreads();   // st1 must be fully read before iter0 prefetches into it

    float o[8][4];
    #pragma unroll
    for (int j = 0; j < 8; j++)
        #pragma unroll
        for (int f = 0; f < 4; f++) o[j][f] = 0.f;
    float m_run[2] = {-1e30f, -1e30f}, l_run[2] = {0.f, 0.f};

    const int krow = (lane & 7) + ((lane >> 4) & 1) * 8;
    const int kcsel = ((lane >> 3) & 1) * 8;
    const int vrow = lane & 15;
    const int vcsel = ((lane >> 4) & 1) * 8;

    for (int it = 0; it < NT_; it++) {
        __nv_bfloat16* stc = (it & 1) ? st1 : st0;

        cpwait0();          // chunk it landed (prefetched a full iteration ago)
        __syncthreads();    // all warps done consuming the other stage
        if (it + 1 < NT_) {
            __nv_bfloat16* d = (it & 1) ? st0 : st1;   // consumed last iter - safe
            #pragma unroll
            for (int i = 0; i < 4; i++) {
                const int id = t + 128*i, r = id >> 3, c = (id & 7) * 8;
                const size_t go = (base + (size_t)(it+1)*64 + r) * HD_ + c;
                cp16p(d + 0*PL_ + r*KSTR + c, khi + go);
                cp16p(d + 1*PL_ + r*KSTR + c, klo + go);
                cp16p(d + 2*PL_ + r*KSTR + c, vhi + go);
                cp16p(d + 3*PL_ + r*KSTR + c, vlo + go);
            }
            cpcommit();
        }

        __nv_bfloat16* Kh = stc;
        __nv_bfloat16* Kl = stc + PL_;
        __nv_bfloat16* Vh = stc + 2*PL_;
        __nv_bfloat16* Vl = stc + 3*PL_;

        // ---- S = Q K^T ----
        float s[8][4];
        #pragma unroll
        for (int j = 0; j < 8; j++)
            #pragma unroll
            for (int f = 0; f < 4; f++) s[j][f] = 0.f;

        #pragma unroll
        for (int kc = 0; kc < 4; kc++) {
            uint32_t kbh[4][4], kbl[4][4];
            #pragma unroll
            for (int j2 = 0; j2 < 4; j2++) {
                const uint32_t off = (16*j2 + krow)*KSTR + kc*16 + kcsel;
                ldmx4(kbh[j2], smem_u32(Kh + off));
                ldmx4(kbl[j2], smem_u32(Kl + off));
            }
            #pragma unroll
            for (int j2 = 0; j2 < 4; j2++) {
                mma16816(s[2*j2],   qh[kc], &kbh[j2][0]);
                mma16816(s[2*j2],   qh[kc], &kbl[j2][0]);
                mma16816(s[2*j2],   ql[kc], &kbh[j2][0]);
                mma16816(s[2*j2+1], qh[kc], &kbh[j2][2]);
                mma16816(s[2*j2+1], qh[kc], &kbl[j2][2]);
                mma16816(s[2*j2+1], ql[kc], &kbh[j2][2]);
            }
        }

        // ---- online softmax (exp2 domain) ----
        #pragma unroll
        for (int r = 0; r < 2; r++) {
            float mx = -1e30f;
            #pragma unroll
            for (int j = 0; j < 8; j++)
                mx = fmaxf(mx, fmaxf(s[j][2*r], s[j][2*r+1]));
            mx *= C2_;
            mx = fmaxf(mx, __shfl_xor_sync(0xffffffffu, mx, 1));
            mx = fmaxf(mx, __shfl_xor_sync(0xffffffffu, mx, 2));
            const float mold = m_run[r];
            const float mnew = fmaxf(mold, mx);
            m_run[r] = mnew;
            float rs = 0.f;
            #pragma unroll
            for (int j = 0; j < 8; j++) {
                float p0 = exp2f(fmaf(s[j][2*r],   C2_, -mnew));
                float p1 = exp2f(fmaf(s[j][2*r+1], C2_, -mnew));
                s[j][2*r] = p0; s[j][2*r+1] = p1;
                rs += p0 + p1;
            }
            rs += __shfl_xor_sync(0xffffffffu, rs, 1);
            rs += __shfl_xor_sync(0xffffffffu, rs, 2);
            const float corr = exp2f(mold - mnew);   // ==1.0 exactly when no update
            l_run[r] = l_run[r] * corr + rs;
            if (__any_sync(0xffffffffu, mnew > mold)) {
                #pragma unroll
                for (int j = 0; j < 8; j++) { o[j][2*r] *= corr; o[j][2*r+1] *= corr; }
            }
        }

        // ---- O += P V ----
        #pragma unroll
        for (int kc = 0; kc < 4; kc++) {
            uint32_t ph[4], pl[4];
            pack2(s[2*kc][0],   s[2*kc][1],   ph[0], pl[0]);
            pack2(s[2*kc][2],   s[2*kc][3],   ph[1], pl[1]);
            pack2(s[2*kc+1][0], s[2*kc+1][1], ph[2], pl[2]);
            pack2(s[2*kc+1][2], s[2*kc+1][3], ph[3], pl[3]);

            uint32_t vbh[4][4], vbl[4][4];
            #pragma unroll
            for (int j2 = 0; j2 < 4; j2++) {
                const uint32_t off = (16*kc + vrow)*KSTR + 16*j2 + vcsel;
                ldmx4t(vbh[j2], smem_u32(Vh + off));
                ldmx4t(vbl[j2], smem_u32(Vl + off));
            }
            #pragma unroll
            for (int j2 = 0; j2 < 4; j2++) {
                mma16816(o[2*j2],   ph, &vbh[j2][0]);
                mma16816(o[2*j2],   ph, &vbl[j2][0]);
                mma16816(o[2*j2],   pl, &vbh[j2][0]);
                mma16816(o[2*j2+1], ph, &vbh[j2][2]);
                mma16816(o[2*j2+1], ph, &vbl[j2][2]);
                mma16816(o[2*j2+1], pl, &vbh[j2][2]);
            }
        }
        // no trailing sync
    }

    // ---- epilogue: normalize + write y hi/lo planes [B,S,D] ----
    const int bb = bh >> 4, hh = bh & 15;
    #pragma unroll
    for (int r = 0; r < 2; r++) {
        const float inv = 1.f / l_run[r];
        const int row = qbase + 16*w + g + 8*r;
        const size_t iy = ((size_t)(bb * S_ + row)) * D_ + hh * HD_ + 2*lmb;
        #pragma unroll
        for (int j = 0; j < 8; j++) {
            uint32_t hi, lo;
            pack2(o[j][2*r] * inv, o[j][2*r+1] * inv, hi, lo);
            *(uint32_t*)(g_yh + iy + 8*j) = hi;
            *(uint32_t*)(g_yl + iy + 8*j) = lo;
        }
    }
}

// ===========================================================================
extern "C" void kernel_launch(void* const* d_in, const int* in_sizes, int n_in,
                              void* d_out, int out_size)
{
    const float* q  = (const float*)d_in[0];
    const float* k  = (const float*)d_in[1];
    const float* v  = (const float*)d_in[2];
    const float* Wq = (const float*)d_in[3];
    const float* bq = (const float*)d_in[4];
    const float* Wk = (const float*)d_in[5];
    const float* bk = (const float*)d_in[6];
    const float* Wv = (const float*)d_in[7];
    const float* bv = (const float*)d_in[8];
    const float* Wo = (const float*)d_in[9];
    const float* bo = (const float*)d_in[10];
    float* out = (float*)d_out;

    static bool attr_done = false;
    if (!attr_done) {
        cudaFuncSetAttribute(attn_mma, cudaFuncAttributeMaxDynamicSharedMemorySize, ATTN_SMEM);
        cudaFuncSetAttribute(proj_qkv, cudaFuncAttributeMaxDynamicSharedMemorySize, PROJ_SMEM);
        cudaFuncSetAttribute(proj_out, cudaFuncAttributeMaxDynamicSharedMemorySize, PROJ_SMEM);
        attr_done = true;
    }

    const int NX4 = (int)(NXE / 4);   // 2097152
    const int NW4 = (int)(NWE / 4);   // 262144

    // split all inputs
    split_x3<<<dim3((NX4 + 255)/256, 3), 256>>>(q, k, v, NX4);
    split_w4<<<dim3((NW4 + 255)/256, 4), 256>>>(Wq, Wk, Wv, Wo, NW4);

    // batched QKV projections (one launch, grid.z = 3)
    proj_qkv<<<dim3(D_/128, NROWS/128, 3), 256, PROJ_SMEM>>>(bq, bk, bv);

    // attention (64 q rows per CTA, 3 CTAs/SM)
    attn_mma<<<dim3(S_/64, B_*H_), 128, ATTN_SMEM>>>();

    // output projection
    proj_out<<<dim3(D_/128, NROWS/128), 256, PROJ_SMEM>>>(bo, out);
}